// round 8
// baseline (speedup 1.0000x reference)
#include <cuda_runtime.h>
#include <cuda_bf16.h>
#include <cstdint>

// auxiliary_loss: loss = 0.2 * (pos*sum_neg - neg*sum_pos) / (pos*neg)
// R8: R7 base (best: 48.6us, 5.82TB/s) + FFMA label-multiply (labels are 0/1),
// 2x v8 loads per stream per iter (64B/stream/thread), float count accum.
// All memory-path variants plateau at 5.6-5.8TB/s -> at chip two-stream read
// ceiling; this round minimizes loop-body issue latency.

#define DETA 0.2

constexpr int RED_BLOCKS  = 1184;   // 148 SMs * 8 CTAs
constexpr int RED_THREADS = 256;

// Scratch (__device__ globals; no allocation).
__device__ float        g_psum_all[RED_BLOCKS];
__device__ float        g_psum_pos[RED_BLOCKS];
__device__ float        g_pcnt[RED_BLOCKS];
__device__ unsigned int g_done = 0;   // reset by last block each call

__device__ __forceinline__ float warp_red_f(float v) {
    #pragma unroll
    for (int o = 16; o > 0; o >>= 1) v += __shfl_down_sync(0xffffffffu, v, o);
    return v;
}
__device__ __forceinline__ double warp_red_d(double v) {
    #pragma unroll
    for (int o = 16; o > 0; o >>= 1) v += __shfl_down_sync(0xffffffffu, v, o);
    return v;
}

// 256-bit vector loads (sm_103a). 32B aligned, read-only.
__device__ __forceinline__ void ldg256_f32(const float* p, float* v) {
    asm volatile("ld.global.nc.v8.f32 {%0,%1,%2,%3,%4,%5,%6,%7}, [%8];"
                 : "=f"(v[0]), "=f"(v[1]), "=f"(v[2]), "=f"(v[3]),
                   "=f"(v[4]), "=f"(v[5]), "=f"(v[6]), "=f"(v[7])
                 : "l"(p));
}
__device__ __forceinline__ void ldg256_s32(const int* p, int* v) {
    asm volatile("ld.global.nc.v8.b32 {%0,%1,%2,%3,%4,%5,%6,%7}, [%8];"
                 : "=r"(v[0]), "=r"(v[1]), "=r"(v[2]), "=r"(v[3]),
                   "=r"(v[4]), "=r"(v[5]), "=r"(v[6]), "=r"(v[7])
                 : "l"(p));
}

__device__ __forceinline__ void acc8(const float* v, const int* l,
                                     float& sa, float& sp, float& cf) {
    sa += ((v[0] + v[1]) + (v[2] + v[3])) + ((v[4] + v[5]) + (v[6] + v[7]));
    float f0 = (float)l[0], f1 = (float)l[1], f2 = (float)l[2], f3 = (float)l[3];
    float f4 = (float)l[4], f5 = (float)l[5], f6 = (float)l[6], f7 = (float)l[7];
    float p = v[0] * f0;
    p = fmaf(v[1], f1, p);
    p = fmaf(v[2], f2, p);
    p = fmaf(v[3], f3, p);
    p = fmaf(v[4], f4, p);
    p = fmaf(v[5], f5, p);
    p = fmaf(v[6], f6, p);
    p = fmaf(v[7], f7, p);
    sp += p;
    cf += ((f0 + f1) + (f2 + f3)) + ((f4 + f5) + (f6 + f7));
}

__global__ __launch_bounds__(RED_THREADS)
void fused_loss_kernel(const float* __restrict__ y,
                       const int*   __restrict__ lab,
                       int nvec16,           // n / 16
                       int tail,             // n % 16
                       float* __restrict__ out,
                       double n_total)
{
    float sa0 = 0.0f, sa1 = 0.0f, sp0 = 0.0f, sp1 = 0.0f;
    float cf0 = 0.0f, cf1 = 0.0f;

    const int stride = gridDim.x * blockDim.x;   // 303104
    for (int i = blockIdx.x * blockDim.x + threadIdx.x; i < nvec16; i += stride) {
        const float* yp = y   + (size_t)i * 16;
        const int*   lp = lab + (size_t)i * 16;
        float v0[8], v1[8];
        int   l0[8], l1[8];
        ldg256_f32(yp,     v0);
        ldg256_f32(yp + 8, v1);
        ldg256_s32(lp,     l0);
        ldg256_s32(lp + 8, l1);
        acc8(v0, l0, sa0, sp0, cf0);
        acc8(v1, l1, sa1, sp1, cf1);
    }

    float sa = sa0 + sa1;
    float sp = sp0 + sp1;
    float cf = cf0 + cf1;

    // Scalar tail (n % 16), handled once by block 0.
    if (blockIdx.x == 0 && (int)threadIdx.x < tail) {
        const float* yt = y   + (size_t)nvec16 * 16;
        const int*   lt = lab + (size_t)nvec16 * 16;
        float v = yt[threadIdx.x];
        int   l = lt[threadIdx.x];
        sa += v;
        float fl = (float)l;
        sp += v * fl;
        cf += fl;
    }

    // Intra-block reduce (float; per-thread counts <= ~120, exact)
    sa = warp_red_f(sa);
    sp = warp_red_f(sp);
    cf = warp_red_f(cf);

    __shared__ float s_sa[RED_THREADS / 32];
    __shared__ float s_sp[RED_THREADS / 32];
    __shared__ float s_c [RED_THREADS / 32];
    __shared__ bool  s_last;
    int wid = threadIdx.x >> 5;
    int lid = threadIdx.x & 31;
    if (lid == 0) { s_sa[wid] = sa; s_sp[wid] = sp; s_c[wid] = cf; }
    __syncthreads();

    if (wid == 0) {
        constexpr int NW = RED_THREADS / 32;
        float a = (lid < NW) ? s_sa[lid] : 0.0f;
        float p = (lid < NW) ? s_sp[lid] : 0.0f;
        float k = (lid < NW) ? s_c [lid] : 0.0f;
        a = warp_red_f(a);
        p = warp_red_f(p);
        k = warp_red_f(k);   // per-block count <= 28336 < 2^24, exact in fp32
        if (lid == 0) {
            g_psum_all[blockIdx.x] = a;
            g_psum_pos[blockIdx.x] = p;
            g_pcnt[blockIdx.x]     = k;
            __threadfence();
            unsigned int t = atomicAdd(&g_done, 1u);
            s_last = (t == (unsigned int)(gridDim.x - 1));
        }
    }
    __syncthreads();

    if (!s_last) return;

    // ---- Last block: finalize (partials L2-hot). Deterministic order. ----
    double dsa = 0.0, dsp = 0.0, dc = 0.0;
    for (int j = threadIdx.x; j < RED_BLOCKS; j += RED_THREADS) {
        dsa += (double)g_psum_all[j];
        dsp += (double)g_psum_pos[j];
        dc  += (double)g_pcnt[j];
    }
    dsa = warp_red_d(dsa);
    dsp = warp_red_d(dsp);
    dc  = warp_red_d(dc);

    __shared__ double d_sa[RED_THREADS / 32], d_sp[RED_THREADS / 32], d_c[RED_THREADS / 32];
    if (lid == 0) { d_sa[wid] = dsa; d_sp[wid] = dsp; d_c[wid] = dc; }
    __syncthreads();

    if (threadIdx.x == 0) {
        double SA = 0.0, SP = 0.0, C = 0.0;
        #pragma unroll
        for (int j = 0; j < RED_THREADS / 32; j++) { SA += d_sa[j]; SP += d_sp[j]; C += d_c[j]; }

        double pos = C;
        double neg = n_total - pos;
        bool valid = (pos > 0.0) && (neg > 0.0);
        double sum_neg = SA - SP;
        double denom = valid ? pos * neg : 1.0;
        double loss = DETA * (pos * sum_neg - neg * SP) / denom;
        out[0] = valid ? (float)loss : 0.0f;

        g_done = 0;   // reset for next graph replay
    }
}

extern "C" void kernel_launch(void* const* d_in, const int* in_sizes, int n_in,
                              void* d_out, int out_size)
{
    const float* y   = (const float*)d_in[0];
    const int*   lab = (const int*)d_in[1];
    int n = in_sizes[0];

    int nvec16 = n >> 4;
    int tail   = n & 15;

    fused_loss_kernel<<<RED_BLOCKS, RED_THREADS>>>(
        y, lab, nvec16, tail, (float*)d_out, (double)n);
}

// round 9
// speedup vs baseline: 1.0718x; 1.0718x over previous
#include <cuda_runtime.h>
#include <cuda_bf16.h>
#include <cstdint>

// auxiliary_loss: loss = 0.2 * (pos*sum_neg - neg*sum_pos) / (pos*neg)
// R9: R7 memory shape (single v8 per stream per iter -- the ONLY shape that
// reaches 5.8TB/s; wider per-thread loads regressed 3x in R2/R5/R8) combined
// with R8's FFMA accumulation body (alu issue 7.5% -> 4.0%).

#define DETA 0.2

constexpr int RED_BLOCKS  = 1184;   // 148 SMs * 8 CTAs
constexpr int RED_THREADS = 256;

// Scratch (__device__ globals; no allocation).
__device__ float        g_psum_all[RED_BLOCKS];
__device__ float        g_psum_pos[RED_BLOCKS];
__device__ float        g_pcnt[RED_BLOCKS];
__device__ unsigned int g_done = 0;   // reset by last block each call

__device__ __forceinline__ float warp_red_f(float v) {
    #pragma unroll
    for (int o = 16; o > 0; o >>= 1) v += __shfl_down_sync(0xffffffffu, v, o);
    return v;
}
__device__ __forceinline__ double warp_red_d(double v) {
    #pragma unroll
    for (int o = 16; o > 0; o >>= 1) v += __shfl_down_sync(0xffffffffu, v, o);
    return v;
}

// 256-bit vector loads (sm_103a). 32B aligned, read-only.
__device__ __forceinline__ void ldg256_f32(const float* p, float* v) {
    asm volatile("ld.global.nc.v8.f32 {%0,%1,%2,%3,%4,%5,%6,%7}, [%8];"
                 : "=f"(v[0]), "=f"(v[1]), "=f"(v[2]), "=f"(v[3]),
                   "=f"(v[4]), "=f"(v[5]), "=f"(v[6]), "=f"(v[7])
                 : "l"(p));
}
__device__ __forceinline__ void ldg256_s32(const int* p, int* v) {
    asm volatile("ld.global.nc.v8.b32 {%0,%1,%2,%3,%4,%5,%6,%7}, [%8];"
                 : "=r"(v[0]), "=r"(v[1]), "=r"(v[2]), "=r"(v[3]),
                   "=r"(v[4]), "=r"(v[5]), "=r"(v[6]), "=r"(v[7])
                 : "l"(p));
}

__global__ __launch_bounds__(RED_THREADS)
void fused_loss_kernel(const float* __restrict__ y,
                       const int*   __restrict__ lab,
                       int nvec8,            // n / 8
                       int tail,             // n % 8
                       float* __restrict__ out,
                       double n_total)
{
    float sa0 = 0.0f, sa1 = 0.0f;
    float sp  = 0.0f;
    float cf0 = 0.0f, cf1 = 0.0f;

    const int stride = gridDim.x * blockDim.x;   // 303104
    for (int i = blockIdx.x * blockDim.x + threadIdx.x; i < nvec8; i += stride) {
        float v[8];
        int   l[8];
        ldg256_f32(y   + (size_t)i * 8, v);
        ldg256_s32(lab + (size_t)i * 8, l);

        sa0 += (v[0] + v[1]) + (v[2] + v[3]);
        sa1 += (v[4] + v[5]) + (v[6] + v[7]);

        // labels are 0/1: FFMA instead of predicated adds.
        float f0 = (float)l[0], f1 = (float)l[1], f2 = (float)l[2], f3 = (float)l[3];
        float f4 = (float)l[4], f5 = (float)l[5], f6 = (float)l[6], f7 = (float)l[7];
        float p0 = v[0] * f0;
        float p1 = v[1] * f1;
        p0 = fmaf(v[2], f2, p0);
        p1 = fmaf(v[3], f3, p1);
        p0 = fmaf(v[4], f4, p0);
        p1 = fmaf(v[5], f5, p1);
        p0 = fmaf(v[6], f6, p0);
        p1 = fmaf(v[7], f7, p1);
        sp += p0 + p1;

        cf0 += (f0 + f1) + (f2 + f3);
        cf1 += (f4 + f5) + (f6 + f7);
    }

    float sa = sa0 + sa1;
    float cf = cf0 + cf1;

    // Scalar tail (n % 8), handled once by block 0.
    if (blockIdx.x == 0 && (int)threadIdx.x < tail) {
        const float* yt = y   + (size_t)nvec8 * 8;
        const int*   lt = lab + (size_t)nvec8 * 8;
        float v = yt[threadIdx.x];
        float fl = (float)lt[threadIdx.x];
        sa += v;
        sp += v * fl;
        cf += fl;
    }

    // Intra-block reduce (fp32; per-thread count <= ~111, block count < 2^24: exact)
    sa = warp_red_f(sa);
    sp = warp_red_f(sp);
    cf = warp_red_f(cf);

    __shared__ float s_sa[RED_THREADS / 32];
    __shared__ float s_sp[RED_THREADS / 32];
    __shared__ float s_c [RED_THREADS / 32];
    __shared__ bool  s_last;
    int wid = threadIdx.x >> 5;
    int lid = threadIdx.x & 31;
    if (lid == 0) { s_sa[wid] = sa; s_sp[wid] = sp; s_c[wid] = cf; }
    __syncthreads();

    if (wid == 0) {
        constexpr int NW = RED_THREADS / 32;
        float a = (lid < NW) ? s_sa[lid] : 0.0f;
        float p = (lid < NW) ? s_sp[lid] : 0.0f;
        float k = (lid < NW) ? s_c [lid] : 0.0f;
        a = warp_red_f(a);
        p = warp_red_f(p);
        k = warp_red_f(k);
        if (lid == 0) {
            g_psum_all[blockIdx.x] = a;
            g_psum_pos[blockIdx.x] = p;
            g_pcnt[blockIdx.x]     = k;
            __threadfence();
            unsigned int t = atomicAdd(&g_done, 1u);
            s_last = (t == (unsigned int)(gridDim.x - 1));
        }
    }
    __syncthreads();

    if (!s_last) return;

    // ---- Last block: finalize (partials L2-hot). Deterministic order. ----
    double dsa = 0.0, dsp = 0.0, dc = 0.0;
    for (int j = threadIdx.x; j < RED_BLOCKS; j += RED_THREADS) {
        dsa += (double)g_psum_all[j];
        dsp += (double)g_psum_pos[j];
        dc  += (double)g_pcnt[j];
    }
    dsa = warp_red_d(dsa);
    dsp = warp_red_d(dsp);
    dc  = warp_red_d(dc);

    __shared__ double d_sa[RED_THREADS / 32], d_sp[RED_THREADS / 32], d_c[RED_THREADS / 32];
    if (lid == 0) { d_sa[wid] = dsa; d_sp[wid] = dsp; d_c[wid] = dc; }
    __syncthreads();

    if (threadIdx.x == 0) {
        double SA = 0.0, SP = 0.0, C = 0.0;
        #pragma unroll
        for (int j = 0; j < RED_THREADS / 32; j++) { SA += d_sa[j]; SP += d_sp[j]; C += d_c[j]; }

        double pos = C;
        double neg = n_total - pos;
        bool valid = (pos > 0.0) && (neg > 0.0);
        double sum_neg = SA - SP;
        double denom = valid ? pos * neg : 1.0;
        double loss = DETA * (pos * sum_neg - neg * SP) / denom;
        out[0] = valid ? (float)loss : 0.0f;

        g_done = 0;   // reset for next graph replay
    }
}

extern "C" void kernel_launch(void* const* d_in, const int* in_sizes, int n_in,
                              void* d_out, int out_size)
{
    const float* y   = (const float*)d_in[0];
    const int*   lab = (const int*)d_in[1];
    int n = in_sizes[0];

    int nvec8 = n >> 3;
    int tail  = n & 7;

    fused_loss_kernel<<<RED_BLOCKS, RED_THREADS>>>(
        y, lab, nvec8, tail, (float*)d_out, (double)n);
}

// round 10
// speedup vs baseline: 1.0979x; 1.0243x over previous
#include <cuda_runtime.h>
#include <cuda_bf16.h>
#include <cstdint>

// auxiliary_loss: loss = 0.2 * (pos*sum_neg - neg*sum_pos) / (pos*neg)
// R10: exact R7 base (measured best: 48.6us, 5.82TB/s, 73.5% DRAM) plus
// L2::256B fetch-granularity hint on the v8 loads. Nine rounds established:
// single 32B load per stream per iter is the optimal shape; body variations
// and memory-path changes (TMA, chunking, unrolls) are neutral or regress.

#define DETA 0.2

constexpr int RED_BLOCKS  = 1184;   // 148 SMs * 8 CTAs
constexpr int RED_THREADS = 256;

// Scratch (__device__ globals; no allocation).
__device__ float        g_psum_all[RED_BLOCKS];
__device__ float        g_psum_pos[RED_BLOCKS];
__device__ int          g_pcnt[RED_BLOCKS];
__device__ unsigned int g_done = 0;   // reset by last block each call

__device__ __forceinline__ float warp_red_f(float v) {
    #pragma unroll
    for (int o = 16; o > 0; o >>= 1) v += __shfl_down_sync(0xffffffffu, v, o);
    return v;
}
__device__ __forceinline__ int warp_red_i(int v) {
    #pragma unroll
    for (int o = 16; o > 0; o >>= 1) v += __shfl_down_sync(0xffffffffu, v, o);
    return v;
}
__device__ __forceinline__ double warp_red_d(double v) {
    #pragma unroll
    for (int o = 16; o > 0; o >>= 1) v += __shfl_down_sync(0xffffffffu, v, o);
    return v;
}

// 256-bit vector loads with 256B L2 fetch-granularity hint (sm_103a).
__device__ __forceinline__ void ldg256_f32(const float* p, float* v) {
    asm volatile("ld.global.nc.L2::256B.v8.f32 {%0,%1,%2,%3,%4,%5,%6,%7}, [%8];"
                 : "=f"(v[0]), "=f"(v[1]), "=f"(v[2]), "=f"(v[3]),
                   "=f"(v[4]), "=f"(v[5]), "=f"(v[6]), "=f"(v[7])
                 : "l"(p));
}
__device__ __forceinline__ void ldg256_s32(const int* p, int* v) {
    asm volatile("ld.global.nc.L2::256B.v8.b32 {%0,%1,%2,%3,%4,%5,%6,%7}, [%8];"
                 : "=r"(v[0]), "=r"(v[1]), "=r"(v[2]), "=r"(v[3]),
                   "=r"(v[4]), "=r"(v[5]), "=r"(v[6]), "=r"(v[7])
                 : "l"(p));
}

__global__ __launch_bounds__(RED_THREADS)
void fused_loss_kernel(const float* __restrict__ y,
                       const int*   __restrict__ lab,
                       int nvec8,            // n / 8
                       int tail,             // n % 8
                       float* __restrict__ out,
                       double n_total)
{
    // Two independent accumulator banks.
    float sa0 = 0.0f, sa1 = 0.0f, sp0 = 0.0f, sp1 = 0.0f;
    int   c0 = 0, c1 = 0;

    const int stride = gridDim.x * blockDim.x;   // 303104
    for (int i = blockIdx.x * blockDim.x + threadIdx.x; i < nvec8; i += stride) {
        float v[8];
        int   l[8];
        ldg256_f32(y   + (size_t)i * 8, v);
        ldg256_s32(lab + (size_t)i * 8, l);

        sa0 += (v[0] + v[1]) + (v[2] + v[3]);
        sa1 += (v[4] + v[5]) + (v[6] + v[7]);
        float p0 = 0.0f, p1 = 0.0f;
        if (l[0]) p0 += v[0];
        if (l[1]) p0 += v[1];
        if (l[2]) p0 += v[2];
        if (l[3]) p0 += v[3];
        if (l[4]) p1 += v[4];
        if (l[5]) p1 += v[5];
        if (l[6]) p1 += v[6];
        if (l[7]) p1 += v[7];
        sp0 += p0; sp1 += p1;
        c0  += (l[0] + l[1]) + (l[2] + l[3]);
        c1  += (l[4] + l[5]) + (l[6] + l[7]);
    }

    float sa = sa0 + sa1;
    float sp = sp0 + sp1;
    int   c  = c0 + c1;

    // Scalar tail (n % 8), handled once by block 0.
    if (blockIdx.x == 0 && (int)threadIdx.x < tail) {
        const float* yt = y   + (size_t)nvec8 * 8;
        const int*   lt = lab + (size_t)nvec8 * 8;
        float v = yt[threadIdx.x];
        int   l = lt[threadIdx.x];
        sa += v;
        if (l) { sp += v; c += 1; }
    }

    // Intra-block reduce
    sa = warp_red_f(sa);
    sp = warp_red_f(sp);
    c  = warp_red_i(c);

    __shared__ float s_sa[RED_THREADS / 32];
    __shared__ float s_sp[RED_THREADS / 32];
    __shared__ int   s_c [RED_THREADS / 32];
    __shared__ bool  s_last;
    int wid = threadIdx.x >> 5;
    int lid = threadIdx.x & 31;
    if (lid == 0) { s_sa[wid] = sa; s_sp[wid] = sp; s_c[wid] = c; }
    __syncthreads();

    if (wid == 0) {
        constexpr int NW = RED_THREADS / 32;
        float a = (lid < NW) ? s_sa[lid] : 0.0f;
        float p = (lid < NW) ? s_sp[lid] : 0.0f;
        int   k = (lid < NW) ? s_c [lid] : 0;
        a = warp_red_f(a);
        p = warp_red_f(p);
        k = warp_red_i(k);
        if (lid == 0) {
            g_psum_all[blockIdx.x] = a;
            g_psum_pos[blockIdx.x] = p;
            g_pcnt[blockIdx.x]     = k;
            __threadfence();
            unsigned int t = atomicAdd(&g_done, 1u);
            s_last = (t == (unsigned int)(gridDim.x - 1));
        }
    }
    __syncthreads();

    if (!s_last) return;

    // ---- Last block: finalize (partials L2-hot). Deterministic order. ----
    double dsa = 0.0, dsp = 0.0;
    long long dc = 0;
    for (int j = threadIdx.x; j < RED_BLOCKS; j += RED_THREADS) {
        dsa += (double)g_psum_all[j];
        dsp += (double)g_psum_pos[j];
        dc  += (long long)g_pcnt[j];
    }
    dsa = warp_red_d(dsa);
    dsp = warp_red_d(dsp);
    #pragma unroll
    for (int o = 16; o > 0; o >>= 1) dc += __shfl_down_sync(0xffffffffu, dc, o);

    __shared__ double d_sa[RED_THREADS / 32], d_sp[RED_THREADS / 32];
    __shared__ long long d_c[RED_THREADS / 32];
    if (lid == 0) { d_sa[wid] = dsa; d_sp[wid] = dsp; d_c[wid] = dc; }
    __syncthreads();

    if (threadIdx.x == 0) {
        double SA = 0.0, SP = 0.0;
        long long C = 0;
        #pragma unroll
        for (int j = 0; j < RED_THREADS / 32; j++) { SA += d_sa[j]; SP += d_sp[j]; C += d_c[j]; }

        double pos = (double)C;
        double neg = n_total - pos;
        bool valid = (pos > 0.0) && (neg > 0.0);
        double sum_neg = SA - SP;
        double denom = valid ? pos * neg : 1.0;
        double loss = DETA * (pos * sum_neg - neg * SP) / denom;
        out[0] = valid ? (float)loss : 0.0f;

        g_done = 0;   // reset for next graph replay
    }
}

extern "C" void kernel_launch(void* const* d_in, const int* in_sizes, int n_in,
                              void* d_out, int out_size)
{
    const float* y   = (const float*)d_in[0];
    const int*   lab = (const int*)d_in[1];
    int n = in_sizes[0];

    int nvec8 = n >> 3;
    int tail  = n & 7;

    fused_loss_kernel<<<RED_BLOCKS, RED_THREADS>>>(
        y, lab, nvec8, tail, (float*)d_out, (double)n);
}

// round 11
// speedup vs baseline: 1.1222x; 1.0222x over previous
#include <cuda_runtime.h>
#include <cuda_bf16.h>
#include <cstdint>

// auxiliary_loss: loss = 0.2 * (pos*sum_neg - neg*sum_pos) / (pos*neg)
// FINAL (R11 = R7, the measured optimum over 10 A/B rounds):
//  - single ld.global.nc.v8 per stream per iteration (MLP_p1=2) -- the only
//    shape that reaches the 5.8TB/s plateau; wider per-thread loads regressed
//    3x (R2/R5/R8); TMA-bulk pipeline was exactly neutral (R6).
//  - fused last-block finalize (double precision) removes the 2nd launch.
//  - 5.8TB/s == LTS-capped roofline for this dual-stream scan per
//    B300_MICROARCH (path-independent ~6300 B/cyc cap x bank efficiency);
//    DRAM% ~73 is the ceiling, not a kernel deficiency.

#define DETA 0.2

constexpr int RED_BLOCKS  = 1184;   // 148 SMs * 8 CTAs
constexpr int RED_THREADS = 256;

// Scratch (__device__ globals; no allocation).
__device__ float        g_psum_all[RED_BLOCKS];
__device__ float        g_psum_pos[RED_BLOCKS];
__device__ int          g_pcnt[RED_BLOCKS];
__device__ unsigned int g_done = 0;   // reset by last block each call

__device__ __forceinline__ float warp_red_f(float v) {
    #pragma unroll
    for (int o = 16; o > 0; o >>= 1) v += __shfl_down_sync(0xffffffffu, v, o);
    return v;
}
__device__ __forceinline__ int warp_red_i(int v) {
    #pragma unroll
    for (int o = 16; o > 0; o >>= 1) v += __shfl_down_sync(0xffffffffu, v, o);
    return v;
}
__device__ __forceinline__ double warp_red_d(double v) {
    #pragma unroll
    for (int o = 16; o > 0; o >>= 1) v += __shfl_down_sync(0xffffffffu, v, o);
    return v;
}

// 256-bit vector loads (sm_103a). 32B aligned, read-only.
__device__ __forceinline__ void ldg256_f32(const float* p, float* v) {
    asm volatile("ld.global.nc.v8.f32 {%0,%1,%2,%3,%4,%5,%6,%7}, [%8];"
                 : "=f"(v[0]), "=f"(v[1]), "=f"(v[2]), "=f"(v[3]),
                   "=f"(v[4]), "=f"(v[5]), "=f"(v[6]), "=f"(v[7])
                 : "l"(p));
}
__device__ __forceinline__ void ldg256_s32(const int* p, int* v) {
    asm volatile("ld.global.nc.v8.b32 {%0,%1,%2,%3,%4,%5,%6,%7}, [%8];"
                 : "=r"(v[0]), "=r"(v[1]), "=r"(v[2]), "=r"(v[3]),
                   "=r"(v[4]), "=r"(v[5]), "=r"(v[6]), "=r"(v[7])
                 : "l"(p));
}

__global__ __launch_bounds__(RED_THREADS)
void fused_loss_kernel(const float* __restrict__ y,
                       const int*   __restrict__ lab,
                       int nvec8,            // n / 8
                       int tail,             // n % 8
                       float* __restrict__ out,
                       double n_total)
{
    // Two independent accumulator banks.
    float sa0 = 0.0f, sa1 = 0.0f, sp0 = 0.0f, sp1 = 0.0f;
    int   c0 = 0, c1 = 0;

    const int stride = gridDim.x * blockDim.x;   // 303104
    for (int i = blockIdx.x * blockDim.x + threadIdx.x; i < nvec8; i += stride) {
        float v[8];
        int   l[8];
        ldg256_f32(y   + (size_t)i * 8, v);
        ldg256_s32(lab + (size_t)i * 8, l);

        sa0 += (v[0] + v[1]) + (v[2] + v[3]);
        sa1 += (v[4] + v[5]) + (v[6] + v[7]);
        float p0 = 0.0f, p1 = 0.0f;
        if (l[0]) p0 += v[0];
        if (l[1]) p0 += v[1];
        if (l[2]) p0 += v[2];
        if (l[3]) p0 += v[3];
        if (l[4]) p1 += v[4];
        if (l[5]) p1 += v[5];
        if (l[6]) p1 += v[6];
        if (l[7]) p1 += v[7];
        sp0 += p0; sp1 += p1;
        c0  += (l[0] + l[1]) + (l[2] + l[3]);
        c1  += (l[4] + l[5]) + (l[6] + l[7]);
    }

    float sa = sa0 + sa1;
    float sp = sp0 + sp1;
    int   c  = c0 + c1;

    // Scalar tail (n % 8), handled once by block 0.
    if (blockIdx.x == 0 && (int)threadIdx.x < tail) {
        const float* yt = y   + (size_t)nvec8 * 8;
        const int*   lt = lab + (size_t)nvec8 * 8;
        float v = yt[threadIdx.x];
        int   l = lt[threadIdx.x];
        sa += v;
        if (l) { sp += v; c += 1; }
    }

    // Intra-block reduce
    sa = warp_red_f(sa);
    sp = warp_red_f(sp);
    c  = warp_red_i(c);

    __shared__ float s_sa[RED_THREADS / 32];
    __shared__ float s_sp[RED_THREADS / 32];
    __shared__ int   s_c [RED_THREADS / 32];
    __shared__ bool  s_last;
    int wid = threadIdx.x >> 5;
    int lid = threadIdx.x & 31;
    if (lid == 0) { s_sa[wid] = sa; s_sp[wid] = sp; s_c[wid] = c; }
    __syncthreads();

    if (wid == 0) {
        constexpr int NW = RED_THREADS / 32;
        float a = (lid < NW) ? s_sa[lid] : 0.0f;
        float p = (lid < NW) ? s_sp[lid] : 0.0f;
        int   k = (lid < NW) ? s_c [lid] : 0;
        a = warp_red_f(a);
        p = warp_red_f(p);
        k = warp_red_i(k);
        if (lid == 0) {
            g_psum_all[blockIdx.x] = a;
            g_psum_pos[blockIdx.x] = p;
            g_pcnt[blockIdx.x]     = k;
            __threadfence();
            unsigned int t = atomicAdd(&g_done, 1u);
            s_last = (t == (unsigned int)(gridDim.x - 1));
        }
    }
    __syncthreads();

    if (!s_last) return;

    // ---- Last block: finalize (partials L2-hot). Deterministic order. ----
    double dsa = 0.0, dsp = 0.0;
    long long dc = 0;
    for (int j = threadIdx.x; j < RED_BLOCKS; j += RED_THREADS) {
        dsa += (double)g_psum_all[j];
        dsp += (double)g_psum_pos[j];
        dc  += (long long)g_pcnt[j];
    }
    dsa = warp_red_d(dsa);
    dsp = warp_red_d(dsp);
    #pragma unroll
    for (int o = 16; o > 0; o >>= 1) dc += __shfl_down_sync(0xffffffffu, dc, o);

    __shared__ double d_sa[RED_THREADS / 32], d_sp[RED_THREADS / 32];
    __shared__ long long d_c[RED_THREADS / 32];
    if (lid == 0) { d_sa[wid] = dsa; d_sp[wid] = dsp; d_c[wid] = dc; }
    __syncthreads();

    if (threadIdx.x == 0) {
        double SA = 0.0, SP = 0.0;
        long long C = 0;
        #pragma unroll
        for (int j = 0; j < RED_THREADS / 32; j++) { SA += d_sa[j]; SP += d_sp[j]; C += d_c[j]; }

        double pos = (double)C;
        double neg = n_total - pos;
        bool valid = (pos > 0.0) && (neg > 0.0);
        double sum_neg = SA - SP;
        double denom = valid ? pos * neg : 1.0;
        double loss = DETA * (pos * sum_neg - neg * SP) / denom;
        out[0] = valid ? (float)loss : 0.0f;

        g_done = 0;   // reset for next graph replay
    }
}

extern "C" void kernel_launch(void* const* d_in, const int* in_sizes, int n_in,
                              void* d_out, int out_size)
{
    const float* y   = (const float*)d_in[0];
    const int*   lab = (const int*)d_in[1];
    int n = in_sizes[0];

    int nvec8 = n >> 3;
    int tail  = n & 7;

    fused_loss_kernel<<<RED_BLOCKS, RED_THREADS>>>(
        y, lab, nvec8, tail, (float*)d_out, (double)n);
}